// round 1
// baseline (speedup 1.0000x reference)
#include <cuda_runtime.h>
#include <math.h>

#define BATCH 4
#define SEQ   2048
#define DIM   1024
#define HEADS 16
#define DH    64
#define INNER 1024
#define MTOT  (BATCH*SEQ)   // 8192
#define QKVN  (3*INNER)     // 3072

// Scratch (allocation-free rule: __device__ globals)
__device__ float g_q[BATCH*HEADS*SEQ*DH];   // [b,h,n,d], pre-scaled by exp(temperature)
__device__ float g_k[BATCH*HEADS*SEQ*DH];
__device__ float g_v[BATCH*HEADS*SEQ*DH];
__device__ float g_ao[MTOT*INNER];          // attention out, [b*n, h*DH]

// ---------------------------------------------------------------------------
// Kernel 1: qkv = x @ W_qkv, scattered to q/k/v in [b,h,n,d] layout.
// 64x64 tile, BK=16, 256 threads, 4x4 register tiles.
// ---------------------------------------------------------------------------
__global__ void __launch_bounds__(256) qkv_gemm_kernel(
    const float* __restrict__ x, const float* __restrict__ w,
    const float* __restrict__ temp)
{
    __shared__ float As[16][64];   // [k][m]
    __shared__ float Bs[16][64];   // [k][n]

    const int t  = threadIdx.x;
    const int tx = t & 15;
    const int ty = t >> 4;
    const int row0 = blockIdx.x * 64;
    const int col0 = blockIdx.y * 64;

    // staging index maps
    const int ar = t >> 2;           // 0..63 (m)
    const int ak = (t & 3) * 4;      // 0,4,8,12 (k)
    const int bk = t >> 4;           // 0..15 (k)
    const int bn = (t & 15) * 4;     // 0..60 (n)

    float acc[4][4];
#pragma unroll
    for (int i = 0; i < 4; i++)
#pragma unroll
        for (int j = 0; j < 4; j++) acc[i][j] = 0.f;

    for (int k0 = 0; k0 < DIM; k0 += 16) {
        float4 a4 = *(const float4*)&x[(row0 + ar) * DIM + k0 + ak];
        As[ak + 0][ar] = a4.x; As[ak + 1][ar] = a4.y;
        As[ak + 2][ar] = a4.z; As[ak + 3][ar] = a4.w;
        *(float4*)&Bs[bk][bn] = *(const float4*)&w[(k0 + bk) * QKVN + col0 + bn];
        __syncthreads();
#pragma unroll
        for (int kk = 0; kk < 16; kk++) {
            float4 av = *(const float4*)&As[kk][ty * 4];
            float4 bv = *(const float4*)&Bs[kk][tx * 4];
            acc[0][0] += av.x * bv.x; acc[0][1] += av.x * bv.y;
            acc[0][2] += av.x * bv.z; acc[0][3] += av.x * bv.w;
            acc[1][0] += av.y * bv.x; acc[1][1] += av.y * bv.y;
            acc[1][2] += av.y * bv.z; acc[1][3] += av.y * bv.w;
            acc[2][0] += av.z * bv.x; acc[2][1] += av.z * bv.y;
            acc[2][2] += av.z * bv.z; acc[2][3] += av.z * bv.w;
            acc[3][0] += av.w * bv.x; acc[3][1] += av.w * bv.y;
            acc[3][2] += av.w * bv.z; acc[3][3] += av.w * bv.w;
        }
        __syncthreads();
    }

    const float scale = __expf(__ldg(temp));
#pragma unroll
    for (int ii = 0; ii < 4; ii++) {
        const int r  = row0 + ty * 4 + ii;
        const int bb = r >> 11;          // / SEQ
        const int nn = r & (SEQ - 1);
#pragma unroll
        for (int jj = 0; jj < 4; jj++) {
            const int c    = col0 + tx * 4 + jj;
            const int part = c >> 10;            // 0:q 1:k 2:v
            const int wcol = c & (INNER - 1);
            const int hh   = wcol >> 6;
            const int dd   = wcol & (DH - 1);
            const int dst  = (((bb * HEADS + hh) * SEQ) + nn) * DH + dd;
            const float v  = acc[ii][jj];
            if (part == 0)      g_q[dst] = v * scale;
            else if (part == 1) g_k[dst] = v;
            else                g_v[dst] = v;
        }
    }
}

// ---------------------------------------------------------------------------
// Kernel 2: flash-style attention with diagonal mask.
// One block per (64 query rows, head, batch). 256 threads, 4x4 tiles.
// Smem: Qs [d][i], KVs (K as [d][j], then V as [j][dc]), Ps [j][i]. 48KB total.
// ---------------------------------------------------------------------------
__global__ void __launch_bounds__(256) attn_kernel()
{
    __shared__ float Qs [64][64];
    __shared__ float KVs[64][64];
    __shared__ float Ps [64][64];

    const int t  = threadIdx.x;
    const int tx = t & 15;
    const int ty = t >> 4;
    const int n0 = blockIdx.x * 64;
    const int h  = blockIdx.y;
    const int b  = blockIdx.z;
    const int bh = b * HEADS + h;

    const float* __restrict__ qp = g_q + (size_t)bh * SEQ * DH;
    const float* __restrict__ kp = g_k + (size_t)bh * SEQ * DH;
    const float* __restrict__ vp = g_v + (size_t)bh * SEQ * DH;

    // stage Q transposed: Qs[d][i]
#pragma unroll
    for (int it = 0; it < 4; it++) {
        const int idx = t + it * 256;
        const int i  = idx >> 4;
        const int dq = (idx & 15) * 4;
        float4 f = *(const float4*)&qp[(n0 + i) * DH + dq];
        Qs[dq + 0][i] = f.x; Qs[dq + 1][i] = f.y;
        Qs[dq + 2][i] = f.z; Qs[dq + 3][i] = f.w;
    }

    float m[4], l[4], o[4][4];
#pragma unroll
    for (int ii = 0; ii < 4; ii++) {
        m[ii] = -1e30f; l[ii] = 0.f;
#pragma unroll
        for (int cc = 0; cc < 4; cc++) o[ii][cc] = 0.f;
    }

    for (int j0 = 0; j0 < SEQ; j0 += 64) {
        __syncthreads();   // protect KVs (prev V) / Ps / Qs(first iter)
        // stage K transposed: KVs[d][j]
#pragma unroll
        for (int it = 0; it < 4; it++) {
            const int idx = t + it * 256;
            const int j  = idx >> 4;
            const int dq = (idx & 15) * 4;
            float4 f = *(const float4*)&kp[(j0 + j) * DH + dq];
            KVs[dq + 0][j] = f.x; KVs[dq + 1][j] = f.y;
            KVs[dq + 2][j] = f.z; KVs[dq + 3][j] = f.w;
        }
        __syncthreads();

        // S = Q @ K^T (q pre-scaled)
        float s[4][4];
#pragma unroll
        for (int ii = 0; ii < 4; ii++)
#pragma unroll
            for (int jj = 0; jj < 4; jj++) s[ii][jj] = 0.f;
#pragma unroll 8
        for (int kk = 0; kk < 64; kk++) {
            float4 av = *(const float4*)&Qs[kk][ty * 4];
            float4 bv = *(const float4*)&KVs[kk][tx * 4];
            s[0][0] += av.x * bv.x; s[0][1] += av.x * bv.y;
            s[0][2] += av.x * bv.z; s[0][3] += av.x * bv.w;
            s[1][0] += av.y * bv.x; s[1][1] += av.y * bv.y;
            s[1][2] += av.y * bv.z; s[1][3] += av.y * bv.w;
            s[2][0] += av.z * bv.x; s[2][1] += av.z * bv.y;
            s[2][2] += av.z * bv.z; s[2][3] += av.z * bv.w;
            s[3][0] += av.w * bv.x; s[3][1] += av.w * bv.y;
            s[3][2] += av.w * bv.z; s[3][3] += av.w * bv.w;
        }

        // diagonal mask + online softmax
#pragma unroll
        for (int ii = 0; ii < 4; ii++) {
            const int gr = n0 + ty * 4 + ii;
#pragma unroll
            for (int jj = 0; jj < 4; jj++) {
                const int gc = j0 + tx * 4 + jj;
                if (gr == gc) s[ii][jj] = -1e30f;
            }
            float mt = fmaxf(fmaxf(s[ii][0], s[ii][1]), fmaxf(s[ii][2], s[ii][3]));
#pragma unroll
            for (int off = 8; off > 0; off >>= 1)
                mt = fmaxf(mt, __shfl_xor_sync(0xffffffffu, mt, off));
            const float mn    = fmaxf(m[ii], mt);
            const float alpha = __expf(m[ii] - mn);
            m[ii] = mn;
            float rs = 0.f;
#pragma unroll
            for (int jj = 0; jj < 4; jj++) {
                const float p = __expf(s[ii][jj] - mn);
                s[ii][jj] = p;
                rs += p;
            }
#pragma unroll
            for (int off = 8; off > 0; off >>= 1)
                rs += __shfl_xor_sync(0xffffffffu, rs, off);
            l[ii] = l[ii] * alpha + rs;
#pragma unroll
            for (int cc = 0; cc < 4; cc++) o[ii][cc] *= alpha;
            // write P transposed: Ps[j][i]
#pragma unroll
            for (int jj = 0; jj < 4; jj++)
                Ps[tx * 4 + jj][ty * 4 + ii] = s[ii][jj];
        }
        __syncthreads();   // S-reads of KVs done, P fully written

        // stage V row-major into KVs[j][dc]
#pragma unroll
        for (int it = 0; it < 4; it++) {
            const int idx = t + it * 256;
            const int j  = idx >> 4;
            const int dq = (idx & 15) * 4;
            *(float4*)&KVs[j][dq] = *(const float4*)&vp[(j0 + j) * DH + dq];
        }
        __syncthreads();

        // O += P @ V
#pragma unroll 8
        for (int kk = 0; kk < 64; kk++) {
            float4 av = *(const float4*)&Ps[kk][ty * 4];
            float4 bv = *(const float4*)&KVs[kk][tx * 4];
            o[0][0] += av.x * bv.x; o[0][1] += av.x * bv.y;
            o[0][2] += av.x * bv.z; o[0][3] += av.x * bv.w;
            o[1][0] += av.y * bv.x; o[1][1] += av.y * bv.y;
            o[1][2] += av.y * bv.z; o[1][3] += av.y * bv.w;
            o[2][0] += av.z * bv.x; o[2][1] += av.z * bv.y;
            o[2][2] += av.z * bv.z; o[2][3] += av.z * bv.w;
            o[3][0] += av.w * bv.x; o[3][1] += av.w * bv.y;
            o[3][2] += av.w * bv.z; o[3][3] += av.w * bv.w;
        }
    }

    // epilogue: normalize and write [b*n, h*DH + dc]
#pragma unroll
    for (int ii = 0; ii < 4; ii++) {
        const float inv = 1.f / l[ii];
        float4 r;
        r.x = o[ii][0] * inv; r.y = o[ii][1] * inv;
        r.z = o[ii][2] * inv; r.w = o[ii][3] * inv;
        const int gr = n0 + ty * 4 + ii;
        *(float4*)&g_ao[((size_t)(b * SEQ + gr)) * INNER + h * DH + tx * 4] = r;
    }
}

// ---------------------------------------------------------------------------
// Kernel 3: out = g_ao @ W_out + b_out
// ---------------------------------------------------------------------------
__global__ void __launch_bounds__(256) out_gemm_kernel(
    const float* __restrict__ w, const float* __restrict__ bias,
    float* __restrict__ out)
{
    __shared__ float As[16][64];
    __shared__ float Bs[16][64];

    const int t  = threadIdx.x;
    const int tx = t & 15;
    const int ty = t >> 4;
    const int row0 = blockIdx.x * 64;
    const int col0 = blockIdx.y * 64;

    const int ar = t >> 2;
    const int ak = (t & 3) * 4;
    const int bk = t >> 4;
    const int bn = (t & 15) * 4;

    float acc[4][4];
#pragma unroll
    for (int i = 0; i < 4; i++)
#pragma unroll
        for (int j = 0; j < 4; j++) acc[i][j] = 0.f;

    for (int k0 = 0; k0 < INNER; k0 += 16) {
        float4 a4 = *(const float4*)&g_ao[(size_t)(row0 + ar) * INNER + k0 + ak];
        As[ak + 0][ar] = a4.x; As[ak + 1][ar] = a4.y;
        As[ak + 2][ar] = a4.z; As[ak + 3][ar] = a4.w;
        *(float4*)&Bs[bk][bn] = *(const float4*)&w[(k0 + bk) * DIM + col0 + bn];
        __syncthreads();
#pragma unroll
        for (int kk = 0; kk < 16; kk++) {
            float4 av = *(const float4*)&As[kk][ty * 4];
            float4 bv = *(const float4*)&Bs[kk][tx * 4];
            acc[0][0] += av.x * bv.x; acc[0][1] += av.x * bv.y;
            acc[0][2] += av.x * bv.z; acc[0][3] += av.x * bv.w;
            acc[1][0] += av.y * bv.x; acc[1][1] += av.y * bv.y;
            acc[1][2] += av.y * bv.z; acc[1][3] += av.y * bv.w;
            acc[2][0] += av.z * bv.x; acc[2][1] += av.z * bv.y;
            acc[2][2] += av.z * bv.z; acc[2][3] += av.z * bv.w;
            acc[3][0] += av.w * bv.x; acc[3][1] += av.w * bv.y;
            acc[3][2] += av.w * bv.z; acc[3][3] += av.w * bv.w;
        }
        __syncthreads();
    }

#pragma unroll
    for (int ii = 0; ii < 4; ii++) {
        const int r = row0 + ty * 4 + ii;
        const int c = col0 + tx * 4;
        float4 bv = *(const float4*)&bias[c];
        float4 rr;
        rr.x = acc[ii][0] + bv.x; rr.y = acc[ii][1] + bv.y;
        rr.z = acc[ii][2] + bv.z; rr.w = acc[ii][3] + bv.w;
        *(float4*)&out[(size_t)r * DIM + c] = rr;
    }
}

// ---------------------------------------------------------------------------
extern "C" void kernel_launch(void* const* d_in, const int* in_sizes, int n_in,
                              void* d_out, int out_size)
{
    const float* x    = (const float*)d_in[0];
    const float* wqkv = (const float*)d_in[1];
    const float* wout = (const float*)d_in[2];
    const float* bout = (const float*)d_in[3];
    const float* temp = (const float*)d_in[4];
    float* out = (float*)d_out;

    qkv_gemm_kernel<<<dim3(MTOT / 64, QKVN / 64), 256>>>(x, wqkv, temp);
    attn_kernel<<<dim3(SEQ / 64, HEADS, BATCH), 256>>>();
    out_gemm_kernel<<<dim3(MTOT / 64, DIM / 64), 256>>>(wout, bout, out);
}

// round 2
// speedup vs baseline: 1.0003x; 1.0003x over previous
#include <cuda_runtime.h>
#include <math.h>

#define BATCH 4
#define SEQ   2048
#define DIM   1024
#define HEADS 16
#define DH    64
#define INNER 1024
#define MTOT  (BATCH*SEQ)   // 8192
#define QKVN  (3*INNER)     // 3072

// Scratch (allocation-free rule: __device__ globals)
__device__ float g_q[BATCH*HEADS*SEQ*DH];   // [b,h,n,d], pre-scaled by exp(temperature)
__device__ float g_k[BATCH*HEADS*SEQ*DH];
__device__ float g_v[BATCH*HEADS*SEQ*DH];
__device__ float g_ao[MTOT*INNER];          // attention out, [b*n, h*DH]

// ---------------------------------------------------------------------------
// Kernel 1: qkv = x @ W_qkv, scattered to q/k/v in [b,h,n,d] layout.
// 64x64 tile, BK=16, 256 threads, 4x4 register tiles.
// ---------------------------------------------------------------------------
__global__ void __launch_bounds__(256) qkv_gemm_kernel(
    const float* __restrict__ x, const float* __restrict__ w,
    const float* __restrict__ temp)
{
    __shared__ float As[16][64];   // [k][m]
    __shared__ float Bs[16][64];   // [k][n]

    const int t  = threadIdx.x;
    const int tx = t & 15;
    const int ty = t >> 4;
    const int row0 = blockIdx.x * 64;
    const int col0 = blockIdx.y * 64;

    // staging index maps
    const int ar = t >> 2;           // 0..63 (m)
    const int ak = (t & 3) * 4;      // 0,4,8,12 (k)
    const int bk = t >> 4;           // 0..15 (k)
    const int bn = (t & 15) * 4;     // 0..60 (n)

    float acc[4][4];
#pragma unroll
    for (int i = 0; i < 4; i++)
#pragma unroll
        for (int j = 0; j < 4; j++) acc[i][j] = 0.f;

    for (int k0 = 0; k0 < DIM; k0 += 16) {
        float4 a4 = *(const float4*)&x[(row0 + ar) * DIM + k0 + ak];
        As[ak + 0][ar] = a4.x; As[ak + 1][ar] = a4.y;
        As[ak + 2][ar] = a4.z; As[ak + 3][ar] = a4.w;
        *(float4*)&Bs[bk][bn] = *(const float4*)&w[(k0 + bk) * QKVN + col0 + bn];
        __syncthreads();
#pragma unroll
        for (int kk = 0; kk < 16; kk++) {
            float4 av = *(const float4*)&As[kk][ty * 4];
            float4 bv = *(const float4*)&Bs[kk][tx * 4];
            acc[0][0] += av.x * bv.x; acc[0][1] += av.x * bv.y;
            acc[0][2] += av.x * bv.z; acc[0][3] += av.x * bv.w;
            acc[1][0] += av.y * bv.x; acc[1][1] += av.y * bv.y;
            acc[1][2] += av.y * bv.z; acc[1][3] += av.y * bv.w;
            acc[2][0] += av.z * bv.x; acc[2][1] += av.z * bv.y;
            acc[2][2] += av.z * bv.z; acc[2][3] += av.z * bv.w;
            acc[3][0] += av.w * bv.x; acc[3][1] += av.w * bv.y;
            acc[3][2] += av.w * bv.z; acc[3][3] += av.w * bv.w;
        }
        __syncthreads();
    }

    const float scale = __expf(__ldg(temp));
#pragma unroll
    for (int ii = 0; ii < 4; ii++) {
        const int r  = row0 + ty * 4 + ii;
        const int bb = r >> 11;          // / SEQ
        const int nn = r & (SEQ - 1);
#pragma unroll
        for (int jj = 0; jj < 4; jj++) {
            const int c    = col0 + tx * 4 + jj;
            const int part = c >> 10;            // 0:q 1:k 2:v
            const int wcol = c & (INNER - 1);
            const int hh   = wcol >> 6;
            const int dd   = wcol & (DH - 1);
            const int dst  = (((bb * HEADS + hh) * SEQ) + nn) * DH + dd;
            const float v  = acc[ii][jj];
            if (part == 0)      g_q[dst] = v * scale;
            else if (part == 1) g_k[dst] = v;
            else                g_v[dst] = v;
        }
    }
}

// ---------------------------------------------------------------------------
// Kernel 2: flash-style attention with diagonal mask.
// One block per (64 query rows, head, batch). 256 threads, 4x4 tiles.
// Smem: Qs [d][i], KVs (K as [d][j], then V as [j][dc]), Ps [j][i]. 48KB total.
// ---------------------------------------------------------------------------
__global__ void __launch_bounds__(256) attn_kernel()
{
    __shared__ float Qs [64][64];
    __shared__ float KVs[64][64];
    __shared__ float Ps [64][64];

    const int t  = threadIdx.x;
    const int tx = t & 15;
    const int ty = t >> 4;
    const int n0 = blockIdx.x * 64;
    const int h  = blockIdx.y;
    const int b  = blockIdx.z;
    const int bh = b * HEADS + h;

    const float* __restrict__ qp = g_q + (size_t)bh * SEQ * DH;
    const float* __restrict__ kp = g_k + (size_t)bh * SEQ * DH;
    const float* __restrict__ vp = g_v + (size_t)bh * SEQ * DH;

    // stage Q transposed: Qs[d][i]
#pragma unroll
    for (int it = 0; it < 4; it++) {
        const int idx = t + it * 256;
        const int i  = idx >> 4;
        const int dq = (idx & 15) * 4;
        float4 f = *(const float4*)&qp[(n0 + i) * DH + dq];
        Qs[dq + 0][i] = f.x; Qs[dq + 1][i] = f.y;
        Qs[dq + 2][i] = f.z; Qs[dq + 3][i] = f.w;
    }

    float m[4], l[4], o[4][4];
#pragma unroll
    for (int ii = 0; ii < 4; ii++) {
        m[ii] = -1e30f; l[ii] = 0.f;
#pragma unroll
        for (int cc = 0; cc < 4; cc++) o[ii][cc] = 0.f;
    }

    for (int j0 = 0; j0 < SEQ; j0 += 64) {
        __syncthreads();   // protect KVs (prev V) / Ps / Qs(first iter)
        // stage K transposed: KVs[d][j]
#pragma unroll
        for (int it = 0; it < 4; it++) {
            const int idx = t + it * 256;
            const int j  = idx >> 4;
            const int dq = (idx & 15) * 4;
            float4 f = *(const float4*)&kp[(j0 + j) * DH + dq];
            KVs[dq + 0][j] = f.x; KVs[dq + 1][j] = f.y;
            KVs[dq + 2][j] = f.z; KVs[dq + 3][j] = f.w;
        }
        __syncthreads();

        // S = Q @ K^T (q pre-scaled)
        float s[4][4];
#pragma unroll
        for (int ii = 0; ii < 4; ii++)
#pragma unroll
            for (int jj = 0; jj < 4; jj++) s[ii][jj] = 0.f;
#pragma unroll 8
        for (int kk = 0; kk < 64; kk++) {
            float4 av = *(const float4*)&Qs[kk][ty * 4];
            float4 bv = *(const float4*)&KVs[kk][tx * 4];
            s[0][0] += av.x * bv.x; s[0][1] += av.x * bv.y;
            s[0][2] += av.x * bv.z; s[0][3] += av.x * bv.w;
            s[1][0] += av.y * bv.x; s[1][1] += av.y * bv.y;
            s[1][2] += av.y * bv.z; s[1][3] += av.y * bv.w;
            s[2][0] += av.z * bv.x; s[2][1] += av.z * bv.y;
            s[2][2] += av.z * bv.z; s[2][3] += av.z * bv.w;
            s[3][0] += av.w * bv.x; s[3][1] += av.w * bv.y;
            s[3][2] += av.w * bv.z; s[3][3] += av.w * bv.w;
        }

        // diagonal mask + online softmax
#pragma unroll
        for (int ii = 0; ii < 4; ii++) {
            const int gr = n0 + ty * 4 + ii;
#pragma unroll
            for (int jj = 0; jj < 4; jj++) {
                const int gc = j0 + tx * 4 + jj;
                if (gr == gc) s[ii][jj] = -1e30f;
            }
            float mt = fmaxf(fmaxf(s[ii][0], s[ii][1]), fmaxf(s[ii][2], s[ii][3]));
#pragma unroll
            for (int off = 8; off > 0; off >>= 1)
                mt = fmaxf(mt, __shfl_xor_sync(0xffffffffu, mt, off));
            const float mn    = fmaxf(m[ii], mt);
            const float alpha = __expf(m[ii] - mn);
            m[ii] = mn;
            float rs = 0.f;
#pragma unroll
            for (int jj = 0; jj < 4; jj++) {
                const float p = __expf(s[ii][jj] - mn);
                s[ii][jj] = p;
                rs += p;
            }
#pragma unroll
            for (int off = 8; off > 0; off >>= 1)
                rs += __shfl_xor_sync(0xffffffffu, rs, off);
            l[ii] = l[ii] * alpha + rs;
#pragma unroll
            for (int cc = 0; cc < 4; cc++) o[ii][cc] *= alpha;
            // write P transposed: Ps[j][i]
#pragma unroll
            for (int jj = 0; jj < 4; jj++)
                Ps[tx * 4 + jj][ty * 4 + ii] = s[ii][jj];
        }
        __syncthreads();   // S-reads of KVs done, P fully written

        // stage V row-major into KVs[j][dc]
#pragma unroll
        for (int it = 0; it < 4; it++) {
            const int idx = t + it * 256;
            const int j  = idx >> 4;
            const int dq = (idx & 15) * 4;
            *(float4*)&KVs[j][dq] = *(const float4*)&vp[(j0 + j) * DH + dq];
        }
        __syncthreads();

        // O += P @ V
#pragma unroll 8
        for (int kk = 0; kk < 64; kk++) {
            float4 av = *(const float4*)&Ps[kk][ty * 4];
            float4 bv = *(const float4*)&KVs[kk][tx * 4];
            o[0][0] += av.x * bv.x; o[0][1] += av.x * bv.y;
            o[0][2] += av.x * bv.z; o[0][3] += av.x * bv.w;
            o[1][0] += av.y * bv.x; o[1][1] += av.y * bv.y;
            o[1][2] += av.y * bv.z; o[1][3] += av.y * bv.w;
            o[2][0] += av.z * bv.x; o[2][1] += av.z * bv.y;
            o[2][2] += av.z * bv.z; o[2][3] += av.z * bv.w;
            o[3][0] += av.w * bv.x; o[3][1] += av.w * bv.y;
            o[3][2] += av.w * bv.z; o[3][3] += av.w * bv.w;
        }
    }

    // epilogue: normalize and write [b*n, h*DH + dc]
#pragma unroll
    for (int ii = 0; ii < 4; ii++) {
        const float inv = 1.f / l[ii];
        float4 r;
        r.x = o[ii][0] * inv; r.y = o[ii][1] * inv;
        r.z = o[ii][2] * inv; r.w = o[ii][3] * inv;
        const int gr = n0 + ty * 4 + ii;
        *(float4*)&g_ao[((size_t)(b * SEQ + gr)) * INNER + h * DH + tx * 4] = r;
    }
}

// ---------------------------------------------------------------------------
// Kernel 3: out = g_ao @ W_out + b_out
// ---------------------------------------------------------------------------
__global__ void __launch_bounds__(256) out_gemm_kernel(
    const float* __restrict__ w, const float* __restrict__ bias,
    float* __restrict__ out)
{
    __shared__ float As[16][64];
    __shared__ float Bs[16][64];

    const int t  = threadIdx.x;
    const int tx = t & 15;
    const int ty = t >> 4;
    const int row0 = blockIdx.x * 64;
    const int col0 = blockIdx.y * 64;

    const int ar = t >> 2;
    const int ak = (t & 3) * 4;
    const int bk = t >> 4;
    const int bn = (t & 15) * 4;

    float acc[4][4];
#pragma unroll
    for (int i = 0; i < 4; i++)
#pragma unroll
        for (int j = 0; j < 4; j++) acc[i][j] = 0.f;

    for (int k0 = 0; k0 < INNER; k0 += 16) {
        float4 a4 = *(const float4*)&g_ao[(size_t)(row0 + ar) * INNER + k0 + ak];
        As[ak + 0][ar] = a4.x; As[ak + 1][ar] = a4.y;
        As[ak + 2][ar] = a4.z; As[ak + 3][ar] = a4.w;
        *(float4*)&Bs[bk][bn] = *(const float4*)&w[(k0 + bk) * DIM + col0 + bn];
        __syncthreads();
#pragma unroll
        for (int kk = 0; kk < 16; kk++) {
            float4 av = *(const float4*)&As[kk][ty * 4];
            float4 bv = *(const float4*)&Bs[kk][tx * 4];
            acc[0][0] += av.x * bv.x; acc[0][1] += av.x * bv.y;
            acc[0][2] += av.x * bv.z; acc[0][3] += av.x * bv.w;
            acc[1][0] += av.y * bv.x; acc[1][1] += av.y * bv.y;
            acc[1][2] += av.y * bv.z; acc[1][3] += av.y * bv.w;
            acc[2][0] += av.z * bv.x; acc[2][1] += av.z * bv.y;
            acc[2][2] += av.z * bv.z; acc[2][3] += av.z * bv.w;
            acc[3][0] += av.w * bv.x; acc[3][1] += av.w * bv.y;
            acc[3][2] += av.w * bv.z; acc[3][3] += av.w * bv.w;
        }
        __syncthreads();
    }

#pragma unroll
    for (int ii = 0; ii < 4; ii++) {
        const int r = row0 + ty * 4 + ii;
        const int c = col0 + tx * 4;
        float4 bv = *(const float4*)&bias[c];
        float4 rr;
        rr.x = acc[ii][0] + bv.x; rr.y = acc[ii][1] + bv.y;
        rr.z = acc[ii][2] + bv.z; rr.w = acc[ii][3] + bv.w;
        *(float4*)&out[(size_t)r * DIM + c] = rr;
    }
}

// ---------------------------------------------------------------------------
extern "C" void kernel_launch(void* const* d_in, const int* in_sizes, int n_in,
                              void* d_out, int out_size)
{
    const float* x    = (const float*)d_in[0];
    const float* wqkv = (const float*)d_in[1];
    const float* wout = (const float*)d_in[2];
    const float* bout = (const float*)d_in[3];
    const float* temp = (const float*)d_in[4];
    float* out = (float*)d_out;

    qkv_gemm_kernel<<<dim3(MTOT / 64, QKVN / 64), 256>>>(x, wqkv, temp);
    attn_kernel<<<dim3(SEQ / 64, HEADS, BATCH), 256>>>();
    out_gemm_kernel<<<dim3(MTOT / 64, DIM / 64), 256>>>(wout, bout, out);
}

// round 3
// speedup vs baseline: 2.7187x; 2.7178x over previous
#include <cuda_runtime.h>
#include <cuda_bf16.h>
#include <math.h>

#define BATCH 4
#define SEQ   2048
#define DIM   1024
#define HEADS 16
#define DH    64
#define INNER 1024
#define MTOT  (BATCH*SEQ)   // 8192
#define QKVN  (3*INNER)     // 3072
#define BH    (BATCH*HEADS) // 64

typedef unsigned int uint32;

// ---------------- packed bf16-pair scratch (hi/lo split) -------------------
__device__ uint32 g_xp  [2][MTOT][DIM/2];     // x packed along k
__device__ uint32 g_wqkv[2][QKVN][DIM/2];     // W_qkv^T packed along k
__device__ uint32 g_wout[2][DIM][INNER/2];    // W_out^T packed along k
__device__ uint32 g_q [2][BH][SEQ][DH/2];     // pairs along d (q pre-scaled)
__device__ uint32 g_k [2][BH][SEQ][DH/2];     // pairs along d
__device__ uint32 g_v [2][BH][SEQ][DH/2];     // pairs along d
__device__ uint32 g_vT[2][BH][DH][SEQ/2];     // pairs along tokens
__device__ uint32 g_ao[2][MTOT][INNER/2];     // attention output packed

// ---------------- helpers ---------------------------------------------------
__device__ __forceinline__ void split_pack(float x, float y, uint32& hi, uint32& lo) {
    __nv_bfloat162 h = __floats2bfloat162_rn(x, y);
    float rx = x - __bfloat162float(h.x);
    float ry = y - __bfloat162float(h.y);
    __nv_bfloat162 l = __floats2bfloat162_rn(rx, ry);
    hi = *reinterpret_cast<uint32*>(&h);
    lo = *reinterpret_cast<uint32*>(&l);
}

__device__ __forceinline__ void mma_bf16(float* c, uint32 a0, uint32 a1, uint32 a2,
                                         uint32 a3, uint32 b0, uint32 b1) {
    asm volatile(
        "mma.sync.aligned.m16n8k16.row.col.f32.bf16.bf16.f32 "
        "{%0,%1,%2,%3},{%4,%5,%6,%7},{%8,%9},{%0,%1,%2,%3};\n"
        : "+f"(c[0]), "+f"(c[1]), "+f"(c[2]), "+f"(c[3])
        : "r"(a0), "r"(a1), "r"(a2), "r"(a3), "r"(b0), "r"(b1));
}

// ---------------- prep kernels ----------------------------------------------
__global__ __launch_bounds__(256) void pack_x_kernel(const float* __restrict__ x) {
    int i = blockIdx.x * 256 + threadIdx.x;   // over MTOT*DIM/2
    float2 v = ((const float2*)x)[i];
    uint32 hi, lo;
    split_pack(v.x, v.y, hi, lo);
    (&g_xp[0][0][0])[i] = hi;
    (&g_xp[1][0][0])[i] = lo;
}

// W [K][N] fp32 -> W^T packed hi/lo [N][K/2]
__global__ __launch_bounds__(256) void pack_wT_kernel(const float* __restrict__ w, int mode) {
    __shared__ float sm[64][65];
    const int K = mode ? INNER : DIM;
    const int N = mode ? DIM : QKVN;
    uint32* __restrict__ thi = mode ? &g_wout[0][0][0] : &g_wqkv[0][0][0];
    uint32* __restrict__ tlo = mode ? &g_wout[1][0][0] : &g_wqkv[1][0][0];
    const int k0 = blockIdx.x * 64, n0 = blockIdx.y * 64;
    const int t = threadIdx.x;
#pragma unroll
    for (int it = 0; it < 4; it++) {
        int idx = t + it * 256;
        int r = idx >> 4, c = (idx & 15) * 4;
        float4 f = *(const float4*)&w[(size_t)(k0 + r) * N + n0 + c];
        sm[r][c] = f.x; sm[r][c+1] = f.y; sm[r][c+2] = f.z; sm[r][c+3] = f.w;
    }
    __syncthreads();
#pragma unroll
    for (int it = 0; it < 8; it++) {
        int idx = t + it * 256;
        int n = idx >> 5, kp = idx & 31;
        uint32 hi, lo;
        split_pack(sm[2*kp][n], sm[2*kp+1][n], hi, lo);
        size_t off = (size_t)(n0 + n) * (K/2) + (k0 >> 1) + kp;
        thi[off] = hi; tlo[off] = lo;
    }
}

// g_v [bh][n][dp] -> g_vT [bh][d][np]
__global__ __launch_bounds__(256) void vT_kernel() {
    __shared__ uint32 sm[2][64][36];
    const int n0 = blockIdx.x * 64, bhi = blockIdx.y;
    const int t = threadIdx.x;
#pragma unroll
    for (int h = 0; h < 2; h++)
#pragma unroll
        for (int it = 0; it < 2; it++) {
            int idx = t + it * 256;
            int r = idx >> 3, c = (idx & 7) * 4;
            *(uint4*)&sm[h][r][c] = *(const uint4*)&g_v[h][bhi][n0 + r][c];
        }
    __syncthreads();
#pragma unroll
    for (int it = 0; it < 16; it++) {
        int idx = t + it * 256;             // 2*64*32 = 4096
        int h = idx >> 11, rem = idx & 2047;
        int d = rem >> 5, npl = rem & 31;
        uint32 w0 = sm[h][2*npl][d >> 1];
        uint32 w1 = sm[h][2*npl + 1][d >> 1];
        uint32 o = (d & 1) ? __byte_perm(w0, w1, 0x7632) : __byte_perm(w0, w1, 0x5410);
        g_vT[h][bhi][d][(n0 >> 1) + npl] = o;
    }
}

// ---------------- shared GEMM mainloop (128x64 tile, BK=32, bf16x3) ---------
__device__ __forceinline__ void gemm_core(
    const uint32* __restrict__ Ah, const uint32* __restrict__ Al,
    const uint32* __restrict__ Bhp, const uint32* __restrict__ Blp,
    const int k2, const int iters,
    uint32 (&As)[2][128][20], uint32 (&Bs)[2][64][20],
    float (&acc)[2][4][4])
{
    const int t = threadIdx.x;
    const int lane = t & 31, warp = t >> 5;
    const int wm = warp & 3, wn = warp >> 2;
    const int g = lane >> 2, tig = lane & 3;
    const int sr = t >> 2, sc = (t & 3) * 4;

    for (int it = 0; it < iters; it++) {
        const int kp0 = it * 16;
        *(uint4*)&As[0][sr][sc]      = *(const uint4*)&Ah[(size_t)sr * k2 + kp0 + sc];
        *(uint4*)&As[0][sr+64][sc]   = *(const uint4*)&Ah[(size_t)(sr+64) * k2 + kp0 + sc];
        *(uint4*)&As[1][sr][sc]      = *(const uint4*)&Al[(size_t)sr * k2 + kp0 + sc];
        *(uint4*)&As[1][sr+64][sc]   = *(const uint4*)&Al[(size_t)(sr+64) * k2 + kp0 + sc];
        *(uint4*)&Bs[0][sr][sc]      = *(const uint4*)&Bhp[(size_t)sr * k2 + kp0 + sc];
        *(uint4*)&Bs[1][sr][sc]      = *(const uint4*)&Blp[(size_t)sr * k2 + kp0 + sc];
        __syncthreads();
#pragma unroll
        for (int s = 0; s < 2; s++) {
            uint32 a[2][2][4];
#pragma unroll
            for (int mt = 0; mt < 2; mt++) {
                const int rm = wm * 32 + mt * 16;
#pragma unroll
                for (int h = 0; h < 2; h++) {
                    a[mt][h][0] = As[h][rm + g]    [s*8 + tig];
                    a[mt][h][1] = As[h][rm + g + 8][s*8 + tig];
                    a[mt][h][2] = As[h][rm + g]    [s*8 + tig + 4];
                    a[mt][h][3] = As[h][rm + g + 8][s*8 + tig + 4];
                }
            }
#pragma unroll
            for (int nt = 0; nt < 4; nt++) {
                const int n = wn * 32 + nt * 8 + g;
                const uint32 b0h = Bs[0][n][s*8+tig], b1h = Bs[0][n][s*8+tig+4];
                const uint32 b0l = Bs[1][n][s*8+tig], b1l = Bs[1][n][s*8+tig+4];
#pragma unroll
                for (int mt = 0; mt < 2; mt++) {
                    mma_bf16(acc[mt][nt], a[mt][0][0], a[mt][0][1], a[mt][0][2], a[mt][0][3], b0h, b1h);
                    mma_bf16(acc[mt][nt], a[mt][0][0], a[mt][0][1], a[mt][0][2], a[mt][0][3], b0l, b1l);
                    mma_bf16(acc[mt][nt], a[mt][1][0], a[mt][1][1], a[mt][1][2], a[mt][1][3], b0h, b1h);
                }
            }
        }
        __syncthreads();
    }
}

// ---------------- kernel 1: QKV projection ----------------------------------
__global__ __launch_bounds__(256, 2) void qkv_gemm_kernel(const float* __restrict__ temp) {
    __shared__ uint32 As[2][128][20];
    __shared__ uint32 Bs[2][64][20];
    const int row0 = blockIdx.x * 128, col0 = blockIdx.y * 64;
    float acc[2][4][4];
#pragma unroll
    for (int i = 0; i < 2; i++)
#pragma unroll
        for (int j = 0; j < 4; j++)
#pragma unroll
            for (int e = 0; e < 4; e++) acc[i][j][e] = 0.f;

    gemm_core(&g_xp[0][row0][0], &g_xp[1][row0][0],
              &g_wqkv[0][col0][0], &g_wqkv[1][col0][0],
              DIM/2, DIM/32, As, Bs, acc);

    const int lane = threadIdx.x & 31, warp = threadIdx.x >> 5;
    const int wm = warp & 3, wn = warp >> 2;
    const int g = lane >> 2, tig = lane & 3;
    const float scale = __expf(__ldg(temp));
#pragma unroll
    for (int mt = 0; mt < 2; mt++) {
        const int m = row0 + wm * 32 + mt * 16 + g;
        const int b = m >> 11, nn = m & (SEQ - 1);
#pragma unroll
        for (int nt = 0; nt < 4; nt++) {
            const int n = col0 + wn * 32 + nt * 8 + tig * 2;
            const int part = n >> 10, wc = n & (INNER - 1);
            const int head = wc >> 6, dd = wc & (DH - 1);
            const int bh = b * HEADS + head, dp = dd >> 1;
#pragma unroll
            for (int slot = 0; slot < 2; slot++) {
                float v0 = acc[mt][nt][slot*2], v1 = acc[mt][nt][slot*2+1];
                if (part == 0) { v0 *= scale; v1 *= scale; }
                uint32 hi, lo;
                split_pack(v0, v1, hi, lo);
                const int row = nn + slot * 8;
                if (part == 0)      { g_q[0][bh][row][dp] = hi; g_q[1][bh][row][dp] = lo; }
                else if (part == 1) { g_k[0][bh][row][dp] = hi; g_k[1][bh][row][dp] = lo; }
                else                { g_v[0][bh][row][dp] = hi; g_v[1][bh][row][dp] = lo; }
            }
        }
    }
}

// ---------------- kernel 2: flash attention (bf16x3 MMA) --------------------
__global__ __launch_bounds__(256, 1) void attn_kernel() {
    __shared__ uint32 Ks[2][64][36];
    __shared__ uint32 Vs[2][64][36];
    const int t = threadIdx.x, lane = t & 31, warp = t >> 5;
    const int g = lane >> 2, tig = lane & 3;
    const int n0 = blockIdx.x * 128;
    const int bh = blockIdx.y;
    const int qrow = n0 + warp * 16;
    const int sr = t >> 2, sc = (t & 3) * 4;

    // Q fragments resident in registers (4 k-steps x hi/lo x 4 regs)
    uint32 qf[4][2][4];
#pragma unroll
    for (int s = 0; s < 4; s++)
#pragma unroll
        for (int h = 0; h < 2; h++) {
            qf[s][h][0] = g_q[h][bh][qrow + g]    [s*8 + tig];
            qf[s][h][1] = g_q[h][bh][qrow + g + 8][s*8 + tig];
            qf[s][h][2] = g_q[h][bh][qrow + g]    [s*8 + tig + 4];
            qf[s][h][3] = g_q[h][bh][qrow + g + 8][s*8 + tig + 4];
        }

    float o[8][4];
#pragma unroll
    for (int dt = 0; dt < 8; dt++)
#pragma unroll
        for (int e = 0; e < 4; e++) o[dt][e] = 0.f;
    float mrow[2] = {-1e30f, -1e30f}, lrow[2] = {0.f, 0.f};

    for (int j0 = 0; j0 < SEQ; j0 += 64) {
        __syncthreads();
#pragma unroll
        for (int h = 0; h < 2; h++) {
            *(uint4*)&Ks[h][sr][sc]      = *(const uint4*)&g_k [h][bh][j0 + sr][sc];
            *(uint4*)&Ks[h][sr][sc + 16] = *(const uint4*)&g_k [h][bh][j0 + sr][sc + 16];
            *(uint4*)&Vs[h][sr][sc]      = *(const uint4*)&g_vT[h][bh][sr][(j0 >> 1) + sc];
            *(uint4*)&Vs[h][sr][sc + 16] = *(const uint4*)&g_vT[h][bh][sr][(j0 >> 1) + sc + 16];
        }
        __syncthreads();

        // S = Q K^T
        float sacc[8][4];
#pragma unroll
        for (int nt = 0; nt < 8; nt++)
#pragma unroll
            for (int e = 0; e < 4; e++) sacc[nt][e] = 0.f;
#pragma unroll
        for (int s = 0; s < 4; s++)
#pragma unroll
            for (int nt = 0; nt < 8; nt++) {
                const int j = nt * 8 + g;
                const uint32 b0h = Ks[0][j][s*8+tig], b1h = Ks[0][j][s*8+tig+4];
                const uint32 b0l = Ks[1][j][s*8+tig], b1l = Ks[1][j][s*8+tig+4];
                mma_bf16(sacc[nt], qf[s][0][0], qf[s][0][1], qf[s][0][2], qf[s][0][3], b0h, b1h);
                mma_bf16(sacc[nt], qf[s][0][0], qf[s][0][1], qf[s][0][2], qf[s][0][3], b0l, b1l);
                mma_bf16(sacc[nt], qf[s][1][0], qf[s][1][1], qf[s][1][2], qf[s][1][3], b0h, b1h);
            }

        // diagonal mask + online softmax (rows g and g+8 per thread-group)
#pragma unroll
        for (int slot = 0; slot < 2; slot++) {
            const int ri = qrow + g + slot * 8;
            float mx = -1e30f;
#pragma unroll
            for (int nt = 0; nt < 8; nt++)
#pragma unroll
                for (int e = 0; e < 2; e++) {
                    const int jg = j0 + nt * 8 + tig * 2 + e;
                    float v = sacc[nt][slot*2 + e];
                    if (jg == ri) v = -1e30f;
                    sacc[nt][slot*2 + e] = v;
                    mx = fmaxf(mx, v);
                }
            mx = fmaxf(mx, __shfl_xor_sync(0xffffffffu, mx, 1));
            mx = fmaxf(mx, __shfl_xor_sync(0xffffffffu, mx, 2));
            const float mn = fmaxf(mrow[slot], mx);
            const float al = __expf(mrow[slot] - mn);
            mrow[slot] = mn;
            float rs = 0.f;
#pragma unroll
            for (int nt = 0; nt < 8; nt++)
#pragma unroll
                for (int e = 0; e < 2; e++) {
                    const float p = __expf(sacc[nt][slot*2 + e] - mn);
                    sacc[nt][slot*2 + e] = p;
                    rs += p;
                }
            rs += __shfl_xor_sync(0xffffffffu, rs, 1);
            rs += __shfl_xor_sync(0xffffffffu, rs, 2);
            lrow[slot] = lrow[slot] * al + rs;
#pragma unroll
            for (int dt = 0; dt < 8; dt++) {
                o[dt][slot*2]     *= al;
                o[dt][slot*2 + 1] *= al;
            }
        }

        // O += P V   (P converted to bf16 hi/lo A-fragments in registers)
#pragma unroll
        for (int s = 0; s < 4; s++) {
            uint32 pah[4], pal[4];
            split_pack(sacc[2*s][0],     sacc[2*s][1],     pah[0], pal[0]);
            split_pack(sacc[2*s][2],     sacc[2*s][3],     pah[1], pal[1]);
            split_pack(sacc[2*s + 1][0], sacc[2*s + 1][1], pah[2], pal[2]);
            split_pack(sacc[2*s + 1][2], sacc[2*s + 1][3], pah[3], pal[3]);
#pragma unroll
            for (int dt = 0; dt < 8; dt++) {
                const int d = dt * 8 + g;
                const uint32 b0h = Vs[0][d][s*8+tig], b1h = Vs[0][d][s*8+tig+4];
                const uint32 b0l = Vs[1][d][s*8+tig], b1l = Vs[1][d][s*8+tig+4];
                mma_bf16(o[dt], pah[0], pah[1], pah[2], pah[3], b0h, b1h);
                mma_bf16(o[dt], pah[0], pah[1], pah[2], pah[3], b0l, b1l);
                mma_bf16(o[dt], pal[0], pal[1], pal[2], pal[3], b0h, b1h);
            }
        }
    }

    // epilogue: normalize + pack to g_ao
    const int b = bh >> 4, head = bh & 15;
    const float inv0 = 1.f / lrow[0], inv1 = 1.f / lrow[1];
#pragma unroll
    for (int dt = 0; dt < 8; dt++) {
        const int ip = head * 32 + dt * 4 + tig;
#pragma unroll
        for (int slot = 0; slot < 2; slot++) {
            const float inv = slot ? inv1 : inv0;
            const int m = b * SEQ + qrow + g + slot * 8;
            uint32 hi, lo;
            split_pack(o[dt][slot*2] * inv, o[dt][slot*2 + 1] * inv, hi, lo);
            g_ao[0][m][ip] = hi;
            g_ao[1][m][ip] = lo;
        }
    }
}

// ---------------- kernel 3: output projection -------------------------------
__global__ __launch_bounds__(256, 2) void out_gemm_kernel(
    const float* __restrict__ bias, float* __restrict__ out)
{
    __shared__ uint32 As[2][128][20];
    __shared__ uint32 Bs[2][64][20];
    const int row0 = blockIdx.x * 128, col0 = blockIdx.y * 64;
    float acc[2][4][4];
#pragma unroll
    for (int i = 0; i < 2; i++)
#pragma unroll
        for (int j = 0; j < 4; j++)
#pragma unroll
            for (int e = 0; e < 4; e++) acc[i][j][e] = 0.f;

    gemm_core(&g_ao[0][row0][0], &g_ao[1][row0][0],
              &g_wout[0][col0][0], &g_wout[1][col0][0],
              INNER/2, INNER/32, As, Bs, acc);

    const int lane = threadIdx.x & 31, warp = threadIdx.x >> 5;
    const int wm = warp & 3, wn = warp >> 2;
    const int g = lane >> 2, tig = lane & 3;
#pragma unroll
    for (int mt = 0; mt < 2; mt++) {
        const int m = row0 + wm * 32 + mt * 16 + g;
#pragma unroll
        for (int nt = 0; nt < 4; nt++) {
            const int n = col0 + wn * 32 + nt * 8 + tig * 2;
            const float b0 = bias[n], b1 = bias[n + 1];
#pragma unroll
            for (int slot = 0; slot < 2; slot++) {
                float2 r;
                r.x = acc[mt][nt][slot*2]     + b0;
                r.y = acc[mt][nt][slot*2 + 1] + b1;
                *(float2*)&out[(size_t)(m + slot * 8) * DIM + n] = r;
            }
        }
    }
}

// ---------------------------------------------------------------------------
extern "C" void kernel_launch(void* const* d_in, const int* in_sizes, int n_in,
                              void* d_out, int out_size)
{
    const float* x    = (const float*)d_in[0];
    const float* wqkv = (const float*)d_in[1];
    const float* wout = (const float*)d_in[2];
    const float* bout = (const float*)d_in[3];
    const float* temp = (const float*)d_in[4];
    float* out = (float*)d_out;

    pack_x_kernel<<<(MTOT * DIM / 2) / 256, 256>>>(x);
    pack_wT_kernel<<<dim3(DIM / 64, QKVN / 64), 256>>>(wqkv, 0);
    pack_wT_kernel<<<dim3(INNER / 64, DIM / 64), 256>>>(wout, 1);
    qkv_gemm_kernel<<<dim3(MTOT / 128, QKVN / 64), 256>>>(temp);
    vT_kernel<<<dim3(SEQ / 64, BH), 256>>>();
    attn_kernel<<<dim3(SEQ / 128, BH), 256>>>();
    out_gemm_kernel<<<dim3(MTOT / 128, DIM / 64), 256>>>(bout, out);
}

// round 4
// speedup vs baseline: 4.0210x; 1.4790x over previous
#include <cuda_runtime.h>
#include <cuda_bf16.h>
#include <math.h>

#define BATCH 4
#define SEQ   2048
#define DIM   1024
#define HEADS 16
#define DH    64
#define INNER 1024
#define MTOT  (BATCH*SEQ)   // 8192
#define QKVN  (3*INNER)     // 3072
#define BH    (BATCH*HEADS) // 64

typedef unsigned int uint32;

// ---------------- packed bf16-pair scratch (hi/lo split) -------------------
__device__ uint32 g_xp  [2][MTOT][DIM/2];
__device__ uint32 g_wqkv[2][QKVN][DIM/2];
__device__ uint32 g_wout[2][DIM][INNER/2];
__device__ uint32 g_q [2][BH][SEQ][DH/2];
__device__ uint32 g_k [2][BH][SEQ][DH/2];
__device__ uint32 g_v [2][BH][SEQ][DH/2];
__device__ uint32 g_vT[2][BH][DH][SEQ/2];
__device__ uint32 g_ao[2][MTOT][INNER/2];

// ---------------- helpers ---------------------------------------------------
__device__ __forceinline__ void split_pack(float x, float y, uint32& hi, uint32& lo) {
    __nv_bfloat162 h = __floats2bfloat162_rn(x, y);
    float rx = x - __bfloat162float(h.x);
    float ry = y - __bfloat162float(h.y);
    __nv_bfloat162 l = __floats2bfloat162_rn(rx, ry);
    hi = *reinterpret_cast<uint32*>(&h);
    lo = *reinterpret_cast<uint32*>(&l);
}

__device__ __forceinline__ void mma_bf16(float* c, uint32 a0, uint32 a1, uint32 a2,
                                         uint32 a3, uint32 b0, uint32 b1) {
    asm volatile(
        "mma.sync.aligned.m16n8k16.row.col.f32.bf16.bf16.f32 "
        "{%0,%1,%2,%3},{%4,%5,%6,%7},{%8,%9},{%0,%1,%2,%3};\n"
        : "+f"(c[0]), "+f"(c[1]), "+f"(c[2]), "+f"(c[3])
        : "r"(a0), "r"(a1), "r"(a2), "r"(a3), "r"(b0), "r"(b1));
}

__device__ __forceinline__ uint32 smem_u32(const void* p) {
    uint32 a;
    asm("{ .reg .u64 t; cvta.to.shared.u64 t, %1; cvt.u32.u64 %0, t; }"
        : "=r"(a) : "l"(p));
    return a;
}

__device__ __forceinline__ uint32 swz(uint32 o) { return o ^ ((o >> 3) & 0x70); }

__device__ __forceinline__ void cpa16(uint32 dst, const void* src) {
    asm volatile("cp.async.cg.shared.global [%0], [%1], 16;\n" :: "r"(dst), "l"(src));
}
__device__ __forceinline__ void cp_commit() { asm volatile("cp.async.commit_group;\n"); }
template<int N> __device__ __forceinline__ void cp_wait() {
    asm volatile("cp.async.wait_group %0;\n" :: "n"(N));
}

__device__ __forceinline__ void ldm4(uint32& r0, uint32& r1, uint32& r2, uint32& r3,
                                     uint32 addr) {
    asm volatile("ldmatrix.sync.aligned.m8n8.x4.shared.b16 {%0,%1,%2,%3},[%4];\n"
        : "=r"(r0), "=r"(r1), "=r"(r2), "=r"(r3) : "r"(addr));
}

// ---------------- prep kernels ----------------------------------------------
__global__ __launch_bounds__(256) void pack_x_kernel(const float* __restrict__ x) {
    int i = blockIdx.x * 256 + threadIdx.x;
    float2 v = ((const float2*)x)[i];
    uint32 hi, lo;
    split_pack(v.x, v.y, hi, lo);
    (&g_xp[0][0][0])[i] = hi;
    (&g_xp[1][0][0])[i] = lo;
}

__global__ __launch_bounds__(256) void pack_wT_kernel(const float* __restrict__ w, int mode) {
    __shared__ float sm[64][65];
    const int K = mode ? INNER : DIM;
    const int N = mode ? DIM : QKVN;
    uint32* __restrict__ thi = mode ? &g_wout[0][0][0] : &g_wqkv[0][0][0];
    uint32* __restrict__ tlo = mode ? &g_wout[1][0][0] : &g_wqkv[1][0][0];
    const int k0 = blockIdx.x * 64, n0 = blockIdx.y * 64;
    const int t = threadIdx.x;
#pragma unroll
    for (int it = 0; it < 4; it++) {
        int idx = t + it * 256;
        int r = idx >> 4, c = (idx & 15) * 4;
        float4 f = *(const float4*)&w[(size_t)(k0 + r) * N + n0 + c];
        sm[r][c] = f.x; sm[r][c+1] = f.y; sm[r][c+2] = f.z; sm[r][c+3] = f.w;
    }
    __syncthreads();
#pragma unroll
    for (int it = 0; it < 8; it++) {
        int idx = t + it * 256;
        int n = idx >> 5, kp = idx & 31;
        uint32 hi, lo;
        split_pack(sm[2*kp][n], sm[2*kp+1][n], hi, lo);
        size_t off = (size_t)(n0 + n) * (K/2) + (k0 >> 1) + kp;
        thi[off] = hi; tlo[off] = lo;
    }
}

__global__ __launch_bounds__(256) void vT_kernel() {
    __shared__ uint32 sm[2][64][36];
    const int n0 = blockIdx.x * 64, bhi = blockIdx.y;
    const int t = threadIdx.x;
#pragma unroll
    for (int h = 0; h < 2; h++)
#pragma unroll
        for (int it = 0; it < 2; it++) {
            int idx = t + it * 256;
            int r = idx >> 3, c = (idx & 7) * 4;
            *(uint4*)&sm[h][r][c] = *(const uint4*)&g_v[h][bhi][n0 + r][c];
        }
    __syncthreads();
#pragma unroll
    for (int it = 0; it < 16; it++) {
        int idx = t + it * 256;
        int h = idx >> 11, rem = idx & 2047;
        int d = rem >> 5, npl = rem & 31;
        uint32 w0 = sm[h][2*npl][d >> 1];
        uint32 w1 = sm[h][2*npl + 1][d >> 1];
        uint32 o = (d & 1) ? __byte_perm(w0, w1, 0x7632) : __byte_perm(w0, w1, 0x5410);
        g_vT[h][bhi][d][(n0 >> 1) + npl] = o;
    }
}

// ---------------- pipelined GEMM (128x128 tile, BK=16, bf16x3, 3-stage) -----
__device__ __forceinline__ void gemm_stage(uint32 sbase, int stage,
    const uint32* __restrict__ Ah, const uint32* __restrict__ Al,
    const uint32* __restrict__ Bh, const uint32* __restrict__ Bl,
    int k2, int kp)
{
    const int t = threadIdx.x;
#pragma unroll
    for (int i = 0; i < 4; i++) {
        int cid = t + i * 256;          // 0..1023
        int tile = cid >> 9;            // 0=A 1=B
        int w = cid & 511;
        int sp = w >> 8;                // split hi/lo
        int r = (w & 255) >> 1;
        int c = w & 1;
        const uint32* src = tile ? (sp ? Bl : Bh) : (sp ? Al : Ah);
        const uint32* sp4 = src + (size_t)r * k2 + kp + c * 4;
        uint32 dst = sbase + ((stage * 4 + tile * 2 + sp) << 12)
                   + swz((uint32)(r * 32 + c * 16));
        cpa16(dst, sp4);
    }
}

__device__ __forceinline__ void gemm_compute(uint32 sbase, int stage,
                                             float (&acc)[2][8][4])
{
    const int lane = threadIdx.x & 31, warp = threadIdx.x >> 5;
    const int wm = warp & 3, wn = warp >> 2;
    const uint32 pb = sbase + (stage << 14);

    const int ra = wm * 32 + (lane & 7) + ((lane >> 3) & 1) * 8;
    const int ca = (lane >> 4) * 16;
    uint32 aH[2][4], aL[2][4];
#pragma unroll
    for (int mt = 0; mt < 2; mt++) {
        uint32 off = swz((uint32)((ra + mt * 16) * 32 + ca));
        ldm4(aH[mt][0], aH[mt][1], aH[mt][2], aH[mt][3], pb + off);
        ldm4(aL[mt][0], aL[mt][1], aL[mt][2], aL[mt][3], pb + 4096 + off);
    }

    const int rbl = (lane & 7) + ((lane >> 4) ? 8 : 0);
    const int cbl = ((lane >> 3) & 1) * 16;
#pragma unroll
    for (int half = 0; half < 2; half++) {
        uint32 bHf[2][4], bLf[2][4];
#pragma unroll
        for (int p = 0; p < 2; p++) {
            int nb = wn * 64 + (half * 2 + p) * 16;
            uint32 off = swz((uint32)((nb + rbl) * 32 + cbl));
            ldm4(bHf[p][0], bHf[p][1], bHf[p][2], bHf[p][3], pb + 8192 + off);
            ldm4(bLf[p][0], bLf[p][1], bLf[p][2], bLf[p][3], pb + 12288 + off);
        }
#pragma unroll
        for (int mt = 0; mt < 2; mt++)
#pragma unroll
            for (int q = 0; q < 4; q++) {
                const int nt = half * 4 + q;
                const uint32 b0h = bHf[q >> 1][(q & 1) * 2], b1h = bHf[q >> 1][(q & 1) * 2 + 1];
                const uint32 b0l = bLf[q >> 1][(q & 1) * 2], b1l = bLf[q >> 1][(q & 1) * 2 + 1];
                mma_bf16(acc[mt][nt], aH[mt][0], aH[mt][1], aH[mt][2], aH[mt][3], b0h, b1h);
                mma_bf16(acc[mt][nt], aH[mt][0], aH[mt][1], aH[mt][2], aH[mt][3], b0l, b1l);
                mma_bf16(acc[mt][nt], aL[mt][0], aL[mt][1], aL[mt][2], aL[mt][3], b0h, b1h);
            }
    }
}

// ---------------- kernel 1: QKV projection ----------------------------------
__global__ __launch_bounds__(256, 2) void qkv_gemm_kernel(const float* __restrict__ temp) {
    __shared__ __align__(128) uint32 smp[3][4][128][8];   // 48KB
    const uint32 sbase = smem_u32(smp);
    const int row0 = blockIdx.x * 128, col0 = blockIdx.y * 128;
    const uint32 *Ah = &g_xp[0][row0][0],   *Al = &g_xp[1][row0][0];
    const uint32 *Bh = &g_wqkv[0][col0][0], *Bl = &g_wqkv[1][col0][0];

    float acc[2][8][4];
#pragma unroll
    for (int i = 0; i < 2; i++)
#pragma unroll
        for (int j = 0; j < 8; j++)
#pragma unroll
            for (int e = 0; e < 4; e++) acc[i][j][e] = 0.f;

    gemm_stage(sbase, 0, Ah, Al, Bh, Bl, DIM/2, 0); cp_commit();
    gemm_stage(sbase, 1, Ah, Al, Bh, Bl, DIM/2, 8); cp_commit();

    for (int it = 0; it < DIM / 16; it++) {
        cp_wait<1>(); __syncthreads();
        gemm_compute(sbase, it % 3, acc);
        if (it + 2 < DIM / 16)
            gemm_stage(sbase, (it + 2) % 3, Ah, Al, Bh, Bl, DIM/2, (it + 2) * 8);
        cp_commit();
    }

    const int lane = threadIdx.x & 31, warp = threadIdx.x >> 5;
    const int wm = warp & 3, wn = warp >> 2;
    const int g = lane >> 2, tig = lane & 3;
    const float scale = __expf(__ldg(temp));
#pragma unroll
    for (int mt = 0; mt < 2; mt++) {
        const int m = row0 + wm * 32 + mt * 16 + g;
        const int b = m >> 11, nn = m & (SEQ - 1);
#pragma unroll
        for (int nt = 0; nt < 8; nt++) {
            const int n = col0 + wn * 64 + nt * 8 + tig * 2;
            const int part = n >> 10, wc = n & (INNER - 1);
            const int head = wc >> 6, dd = wc & (DH - 1);
            const int bhx = b * HEADS + head, dp = dd >> 1;
#pragma unroll
            for (int slot = 0; slot < 2; slot++) {
                float v0 = acc[mt][nt][slot*2], v1 = acc[mt][nt][slot*2+1];
                if (part == 0) { v0 *= scale; v1 *= scale; }
                uint32 hi, lo;
                split_pack(v0, v1, hi, lo);
                const int row = nn + slot * 8;
                if (part == 0)      { g_q[0][bhx][row][dp] = hi; g_q[1][bhx][row][dp] = lo; }
                else if (part == 1) { g_k[0][bhx][row][dp] = hi; g_k[1][bhx][row][dp] = lo; }
                else                { g_v[0][bhx][row][dp] = hi; g_v[1][bhx][row][dp] = lo; }
            }
        }
    }
}

// ---------------- kernel 2: flash attention (pipelined, ldmatrix) -----------
__device__ __forceinline__ void attn_stage_k(uint32 kb, int bh, int j0) {
    const int t = threadIdx.x;
#pragma unroll
    for (int i = 0; i < 4; i++) {
        int cid = t + i * 256;
        int sp = cid >> 9, w = cid & 511;
        int r = w >> 3, cb = w & 7;
        cpa16(kb + sp * 8192 + swz((uint32)(r * 128 + cb * 16)),
              &g_k[sp][bh][j0 + r][cb * 4]);
    }
}
__device__ __forceinline__ void attn_stage_v(uint32 vb, int bh, int j0) {
    const int t = threadIdx.x;
#pragma unroll
    for (int i = 0; i < 4; i++) {
        int cid = t + i * 256;
        int sp = cid >> 9, w = cid & 511;
        int r = w >> 3, cb = w & 7;
        cpa16(vb + sp * 8192 + swz((uint32)(r * 128 + cb * 16)),
              &g_vT[sp][bh][r][(j0 >> 1) + cb * 4]);
    }
}

__global__ __launch_bounds__(256, 1) void attn_kernel() {
    __shared__ __align__(128) uint32 sk[2][64][32];   // 16KB
    __shared__ __align__(128) uint32 sv[2][64][32];   // 16KB
    const int t = threadIdx.x, lane = t & 31, warp = t >> 5;
    const int g = lane >> 2, tig = lane & 3;
    const int n0 = blockIdx.x * 128, bh = blockIdx.y;
    const int qrow = n0 + warp * 16;
    const uint32 kb = smem_u32(sk), vb = smem_u32(sv);

    uint32 qf[4][2][4];
#pragma unroll
    for (int s = 0; s < 4; s++)
#pragma unroll
        for (int h = 0; h < 2; h++) {
            qf[s][h][0] = g_q[h][bh][qrow + g]    [s*8 + tig];
            qf[s][h][1] = g_q[h][bh][qrow + g + 8][s*8 + tig];
            qf[s][h][2] = g_q[h][bh][qrow + g]    [s*8 + tig + 4];
            qf[s][h][3] = g_q[h][bh][qrow + g + 8][s*8 + tig + 4];
        }

    float o[8][4];
#pragma unroll
    for (int dt = 0; dt < 8; dt++)
#pragma unroll
        for (int e = 0; e < 4; e++) o[dt][e] = 0.f;
    float mrow[2] = {-1e30f, -1e30f}, lrow[2] = {0.f, 0.f};

    attn_stage_k(kb, bh, 0); cp_commit();
    attn_stage_v(vb, bh, 0); cp_commit();

    const int rkl = (lane & 7) + ((lane >> 4) ? 8 : 0);
    const int ckl = ((lane >> 3) & 1) * 16;

    for (int j0 = 0; j0 < SEQ; j0 += 64) {
        cp_wait<1>(); __syncthreads();          // K tile ready

        float sacc[8][4];
#pragma unroll
        for (int nt = 0; nt < 8; nt++)
#pragma unroll
            for (int e = 0; e < 4; e++) sacc[nt][e] = 0.f;

#pragma unroll
        for (int s = 0; s < 4; s++) {
            uint32 bHf[4][4], bLf[4][4];
#pragma unroll
            for (int p = 0; p < 4; p++) {
                uint32 off = swz((uint32)((p * 16 + rkl) * 128 + s * 32 + ckl));
                ldm4(bHf[p][0], bHf[p][1], bHf[p][2], bHf[p][3], kb + off);
                ldm4(bLf[p][0], bLf[p][1], bLf[p][2], bLf[p][3], kb + 8192 + off);
            }
#pragma unroll
            for (int nt = 0; nt < 8; nt++) {
                const uint32 b0h = bHf[nt >> 1][(nt & 1) * 2], b1h = bHf[nt >> 1][(nt & 1) * 2 + 1];
                const uint32 b0l = bLf[nt >> 1][(nt & 1) * 2], b1l = bLf[nt >> 1][(nt & 1) * 2 + 1];
                mma_bf16(sacc[nt], qf[s][0][0], qf[s][0][1], qf[s][0][2], qf[s][0][3], b0h, b1h);
                mma_bf16(sacc[nt], qf[s][0][0], qf[s][0][1], qf[s][0][2], qf[s][0][3], b0l, b1l);
                mma_bf16(sacc[nt], qf[s][1][0], qf[s][1][1], qf[s][1][2], qf[s][1][3], b0h, b1h);
            }
        }
        __syncthreads();                         // done reading K
        if (j0 + 64 < SEQ) attn_stage_k(kb, bh, j0 + 64);
        cp_commit();                             // K(j+1) overlaps softmax+PV

        // diagonal mask + online softmax
#pragma unroll
        for (int slot = 0; slot < 2; slot++) {
            const int ri = qrow + g + slot * 8;
            float mx = -1e30f;
#pragma unroll
            for (int nt = 0; nt < 8; nt++)
#pragma unroll
                for (int e = 0; e < 2; e++) {
                    const int jg = j0 + nt * 8 + tig * 2 + e;
                    float v = sacc[nt][slot*2 + e];
                    if (jg == ri) v = -1e30f;
                    sacc[nt][slot*2 + e] = v;
                    mx = fmaxf(mx, v);
                }
            mx = fmaxf(mx, __shfl_xor_sync(0xffffffffu, mx, 1));
            mx = fmaxf(mx, __shfl_xor_sync(0xffffffffu, mx, 2));
            const float mn = fmaxf(mrow[slot], mx);
            const float al = __expf(mrow[slot] - mn);
            mrow[slot] = mn;
            float rs = 0.f;
#pragma unroll
            for (int nt = 0; nt < 8; nt++)
#pragma unroll
                for (int e = 0; e < 2; e++) {
                    const float p = __expf(sacc[nt][slot*2 + e] - mn);
                    sacc[nt][slot*2 + e] = p;
                    rs += p;
                }
            rs += __shfl_xor_sync(0xffffffffu, rs, 1);
            rs += __shfl_xor_sync(0xffffffffu, rs, 2);
            lrow[slot] = lrow[slot] * al + rs;
#pragma unroll
            for (int dt = 0; dt < 8; dt++) {
                o[dt][slot*2]     *= al;
                o[dt][slot*2 + 1] *= al;
            }
        }

        cp_wait<1>(); __syncthreads();          // V tile ready (K(j+1) may pend)

#pragma unroll
        for (int s = 0; s < 4; s++) {
            uint32 pah[4], pal[4];
            split_pack(sacc[2*s][0],     sacc[2*s][1],     pah[0], pal[0]);
            split_pack(sacc[2*s][2],     sacc[2*s][3],     pah[1], pal[1]);
            split_pack(sacc[2*s + 1][0], sacc[2*s + 1][1], pah[2], pal[2]);
            split_pack(sacc[2*s + 1][2], sacc[2*s + 1][3], pah[3], pal[3]);
            uint32 vHf[4][4], vLf[4][4];
#pragma unroll
            for (int p = 0; p < 4; p++) {
                uint32 off = swz((uint32)((p * 16 + rkl) * 128 + s * 32 + ckl));
                ldm4(vHf[p][0], vHf[p][1], vHf[p][2], vHf[p][3], vb + off);
                ldm4(vLf[p][0], vLf[p][1], vLf[p][2], vLf[p][3], vb + 8192 + off);
            }
#pragma unroll
            for (int dt = 0; dt < 8; dt++) {
                const uint32 b0h = vHf[dt >> 1][(dt & 1) * 2], b1h = vHf[dt >> 1][(dt & 1) * 2 + 1];
                const uint32 b0l = vLf[dt >> 1][(dt & 1) * 2], b1l = vLf[dt >> 1][(dt & 1) * 2 + 1];
                mma_bf16(o[dt], pah[0], pah[1], pah[2], pah[3], b0h, b1h);
                mma_bf16(o[dt], pah[0], pah[1], pah[2], pah[3], b0l, b1l);
                mma_bf16(o[dt], pal[0], pal[1], pal[2], pal[3], b0h, b1h);
            }
        }
        __syncthreads();                         // done reading V
        if (j0 + 64 < SEQ) attn_stage_v(vb, bh, j0 + 64);
        cp_commit();                             // V(j+1) overlaps next QK
    }

    const int b = bh >> 4, head = bh & 15;
    const float inv0 = 1.f / lrow[0], inv1 = 1.f / lrow[1];
#pragma unroll
    for (int dt = 0; dt < 8; dt++) {
        const int ip = head * 32 + dt * 4 + tig;
#pragma unroll
        for (int slot = 0; slot < 2; slot++) {
            const float inv = slot ? inv1 : inv0;
            const int m = b * SEQ + qrow + g + slot * 8;
            uint32 hi, lo;
            split_pack(o[dt][slot*2] * inv, o[dt][slot*2 + 1] * inv, hi, lo);
            g_ao[0][m][ip] = hi;
            g_ao[1][m][ip] = lo;
        }
    }
}

// ---------------- kernel 3: output projection -------------------------------
__global__ __launch_bounds__(256, 2) void out_gemm_kernel(
    const float* __restrict__ bias, float* __restrict__ out)
{
    __shared__ __align__(128) uint32 smp[3][4][128][8];   // 48KB
    const uint32 sbase = smem_u32(smp);
    const int row0 = blockIdx.x * 128, col0 = blockIdx.y * 128;
    const uint32 *Ah = &g_ao[0][row0][0],   *Al = &g_ao[1][row0][0];
    const uint32 *Bh = &g_wout[0][col0][0], *Bl = &g_wout[1][col0][0];

    float acc[2][8][4];
#pragma unroll
    for (int i = 0; i < 2; i++)
#pragma unroll
        for (int j = 0; j < 8; j++)
#pragma unroll
            for (int e = 0; e < 4; e++) acc[i][j][e] = 0.f;

    gemm_stage(sbase, 0, Ah, Al, Bh, Bl, INNER/2, 0); cp_commit();
    gemm_stage(sbase, 1, Ah, Al, Bh, Bl, INNER/2, 8); cp_commit();

    for (int it = 0; it < INNER / 16; it++) {
        cp_wait<1>(); __syncthreads();
        gemm_compute(sbase, it % 3, acc);
        if (it + 2 < INNER / 16)
            gemm_stage(sbase, (it + 2) % 3, Ah, Al, Bh, Bl, INNER/2, (it + 2) * 8);
        cp_commit();
    }

    const int lane = threadIdx.x & 31, warp = threadIdx.x >> 5;
    const int wm = warp & 3, wn = warp >> 2;
    const int g = lane >> 2, tig = lane & 3;
#pragma unroll
    for (int mt = 0; mt < 2; mt++) {
        const int m = row0 + wm * 32 + mt * 16 + g;
#pragma unroll
        for (int nt = 0; nt < 8; nt++) {
            const int n = col0 + wn * 64 + nt * 8 + tig * 2;
            const float b0 = bias[n], b1 = bias[n + 1];
#pragma unroll
            for (int slot = 0; slot < 2; slot++) {
                float2 r;
                r.x = acc[mt][nt][slot*2]     + b0;
                r.y = acc[mt][nt][slot*2 + 1] + b1;
                *(float2*)&out[(size_t)(m + slot * 8) * DIM + n] = r;
            }
        }
    }
}

// ---------------------------------------------------------------------------
extern "C" void kernel_launch(void* const* d_in, const int* in_sizes, int n_in,
                              void* d_out, int out_size)
{
    const float* x    = (const float*)d_in[0];
    const float* wqkv = (const float*)d_in[1];
    const float* wout = (const float*)d_in[2];
    const float* bout = (const float*)d_in[3];
    const float* temp = (const float*)d_in[4];
    float* out = (float*)d_out;

    pack_x_kernel<<<(MTOT * DIM / 2) / 256, 256>>>(x);
    pack_wT_kernel<<<dim3(DIM / 64, QKVN / 64), 256>>>(wqkv, 0);
    pack_wT_kernel<<<dim3(INNER / 64, DIM / 64), 256>>>(wout, 1);
    qkv_gemm_kernel<<<dim3(MTOT / 128, QKVN / 128), 256>>>(temp);
    vT_kernel<<<dim3(SEQ / 64, BH), 256>>>();
    attn_kernel<<<dim3(SEQ / 128, BH), 256>>>();
    out_gemm_kernel<<<dim3(MTOT / 128, DIM / 128), 256>>>(bout, out);
}